// round 3
// baseline (speedup 1.0000x reference)
#include <cuda_runtime.h>
#include <cstdint>

#define B_   32
#define S_   512
#define I_   512
#define H_   512
#define G4_  2048   // 4*H

#define HT_ELEMS 16777216u            // B*S*2H
#define SH_OFF   16777216u            // stacked_h offset
#define SC_OFF   (16777216u + 32768u) // stacked_c offset

// ---------------- device scratch (allocations are forbidden) ----------------
__device__ __align__(16) float g_pre[(size_t)2 * S_ * B_ * G4_]; // [dir][t][b][4H], 256 MB
__device__ __align__(16) float g_hbuf[2][2][B_ * H_];            // [dir][buf][b*512+k]
__device__ unsigned int       g_bar[2];

// ---------------- init: reset barrier + h state every launch ----------------
__global__ void init_kernel() {
    int idx = blockIdx.x * blockDim.x + threadIdx.x;
    if (idx < 2 * 2 * B_ * H_) ((float*)g_hbuf)[idx] = 0.0f;
    if (idx < 2) g_bar[idx] = 0u;
}

// ---------------- phase 1: G = X @ Wih^T + (bih+bhh) ----------------
// C tile 128(m) x 64(n), K-tile 16, 256 threads, 8x4 microtile.
// m = t*32 + b ; A row for m is X[b][t][:]  -> output lands [d][t][b][4H].
__global__ __launch_bounds__(256) void xgemm_kernel(
    const float* __restrict__ X,
    const float* __restrict__ Wih0, const float* __restrict__ bih0, const float* __restrict__ bhh0,
    const float* __restrict__ Wih1, const float* __restrict__ bih1, const float* __restrict__ bhh1)
{
    const int d = blockIdx.z;
    const float* __restrict__ Wih = d ? Wih1 : Wih0;
    const float* __restrict__ bih = d ? bih1 : bih0;
    const float* __restrict__ bhh = d ? bhh1 : bhh0;

    __shared__ __align__(16) float As[16][132];  // [k][m], padded
    __shared__ __align__(16) float Bs[16][68];   // [k][n], padded

    const int tid = threadIdx.x;
    const int m0  = blockIdx.y * 128;
    const int n0  = blockIdx.x * 64;

    // A loader: 512 float4 (128 rows x 16 k), 2 per thread
    int pa0 = tid, pa1 = tid + 256;
    int lmA0 = pa0 >> 2, lkA0 = (pa0 & 3) << 2;
    int lmA1 = pa1 >> 2, lkA1 = (pa1 & 3) << 2;
    int mg0 = m0 + lmA0, mg1 = m0 + lmA1;
    const float* arow0 = X + ((size_t)(mg0 & 31) * S_ + (mg0 >> 5)) * I_;
    const float* arow1 = X + ((size_t)(mg1 & 31) * S_ + (mg1 >> 5)) * I_;
    // B loader: 256 float4 (64 rows x 16 k), 1 per thread
    int lmB = tid >> 2, lkB = (tid & 3) << 2;
    const float* wrow = Wih + (size_t)(n0 + lmB) * I_;

    const int ty = tid >> 4;          // 0..15
    const int tx = tid & 15;          // 0..15
    const int mi = ty << 3;           // 8 rows
    const int ni = tx << 2;           // 4 cols

    float acc[8][4];
#pragma unroll
    for (int i = 0; i < 8; i++)
#pragma unroll
        for (int j = 0; j < 4; j++) acc[i][j] = 0.0f;

    for (int k0 = 0; k0 < I_; k0 += 16) {
        float4 av0 = *(const float4*)(arow0 + k0 + lkA0);
        float4 av1 = *(const float4*)(arow1 + k0 + lkA1);
        float4 bv  = *(const float4*)(wrow  + k0 + lkB);
        __syncthreads();
        As[lkA0 + 0][lmA0] = av0.x; As[lkA0 + 1][lmA0] = av0.y;
        As[lkA0 + 2][lmA0] = av0.z; As[lkA0 + 3][lmA0] = av0.w;
        As[lkA1 + 0][lmA1] = av1.x; As[lkA1 + 1][lmA1] = av1.y;
        As[lkA1 + 2][lmA1] = av1.z; As[lkA1 + 3][lmA1] = av1.w;
        Bs[lkB + 0][lmB] = bv.x; Bs[lkB + 1][lmB] = bv.y;
        Bs[lkB + 2][lmB] = bv.z; Bs[lkB + 3][lmB] = bv.w;
        __syncthreads();
#pragma unroll
        for (int k = 0; k < 16; k++) {
            float4 a0 = *(const float4*)&As[k][mi];
            float4 a1 = *(const float4*)&As[k][mi + 4];
            float4 b  = *(const float4*)&Bs[k][ni];
            float am[8] = {a0.x, a0.y, a0.z, a0.w, a1.x, a1.y, a1.z, a1.w};
            float bn[4] = {b.x, b.y, b.z, b.w};
#pragma unroll
            for (int i = 0; i < 8; i++)
#pragma unroll
                for (int j = 0; j < 4; j++)
                    acc[i][j] = fmaf(am[i], bn[j], acc[i][j]);
        }
    }

    float bz[4];
#pragma unroll
    for (int j = 0; j < 4; j++) bz[j] = bih[n0 + ni + j] + bhh[n0 + ni + j];

#pragma unroll
    for (int i = 0; i < 8; i++) {
        int m = m0 + mi + i;
        int t = m >> 5, bb = m & 31;
        float* dst = g_pre + ((((size_t)d * S_ + t) * B_ + bb) << 11) + n0 + ni;
        float4 o;
        o.x = acc[i][0] + bz[0]; o.y = acc[i][1] + bz[1];
        o.z = acc[i][2] + bz[2]; o.w = acc[i][3] + bz[3];
        *(float4*)dst = o;
    }
}

// ---------------- activations (fp32, ~2^-21 rel err) ----------------
__device__ __forceinline__ float sigm_(float x) {
    x = fminf(fmaxf(x, -30.0f), 30.0f);
    return __fdividef(1.0f, 1.0f + __expf(-x));
}
__device__ __forceinline__ float tanh_(float x) {
    x = fminf(fmaxf(x, -15.0f), 15.0f);
    float e = __expf(-2.0f * x);
    return __fdividef(1.0f - e, 1.0f + e);
}

// ---------------- phase 2: persistent recurrence ----------------
// grid (64, 2). CTA (q,d) owns hidden units j0=8q..8q+7 and computes all 4
// gates for them (gate rows g*512 + j0 + jl). One grid barrier per step.
__global__ __launch_bounds__(256, 1) void recur_kernel(
    const float* __restrict__ Whh_f, const float* __restrict__ Whh_b,
    float* __restrict__ out)
{
    extern __shared__ float sm[];
    float* whT   = sm;                 // [512][33]  (Whh slice, transposed, pad 33)
    float* hsT   = sm + 512 * 33;      // [512][33]  (h, transposed, pad 33)
    float* red   = sm + 2 * 512 * 33;  // [4][1024]  k-split partials
    float* gates = red + 4096;         // [1024]     b*32 + r

    const int tid = threadIdx.x;
    const int q   = blockIdx.x;        // 0..63
    const int d   = blockIdx.y;        // 0..1
    const int j0  = q << 3;
    const float* __restrict__ Whh = d ? Whh_b : Whh_f;

    // Load Whh slice transposed: whT[k][r] = Whh[grow(r)][k]
    for (int e = tid; e < 32 * 512; e += 256) {
        int r = e >> 9, k = e & 511;
        int grow = ((r >> 3) << 9) + j0 + (r & 7);
        whT[k * 33 + r] = Whh[(size_t)grow * 512 + k];
    }

    // GEMM thread tiling: 8x8 grid of (4b x 4r) tiles, 4-way k-split
    const int tileIdx = tid & 63;
    const int ks = tid >> 6;
    const int bt = (tileIdx & 7) << 2;
    const int nt = (tileIdx >> 3) << 2;

    // activation ownership: one (b, jl) per thread
    const int ab  = tid >> 3;
    const int ajl = tid & 7;
    float c_reg = 0.0f;

    for (int s = 0; s < S_; s++) {
        const int t = d ? (S_ - 1 - s) : s;

        // load h (double buffer) into hsT, L2-coherent
        const float* hsrc = &g_hbuf[d][s & 1][0];
        for (int e = tid; e < B_ * H_; e += 256) {
            int b = e >> 9, k = e & 511;
            hsT[k * 33 + b] = __ldcg(hsrc + e);
        }

        // prefetch this step's pre-activations
        float gp[4];
        const float* gpt = g_pre + ((size_t)(d * S_ + t) * B_) * (size_t)G4_;
#pragma unroll
        for (int ii = 0; ii < 4; ii++) {
            int o = tid + (ii << 8);
            int b = o >> 5, r = o & 31;
            gp[ii] = gpt[(size_t)b * G4_ + ((r >> 3) << 9) + j0 + (r & 7)];
        }
        __syncthreads();

        // partial GEMM: acc[i][j] += h[bt+i][k] * Whh[nt+j][k], k in this split
        float acc[4][4];
#pragma unroll
        for (int i = 0; i < 4; i++)
#pragma unroll
            for (int j = 0; j < 4; j++) acc[i][j] = 0.0f;

        const float* hp = hsT + ks * 128 * 33;
        const float* wp = whT + ks * 128 * 33;
#pragma unroll 4
        for (int k = 0; k < 128; k++) {
            float hv[4], wv[4];
#pragma unroll
            for (int i = 0; i < 4; i++) hv[i] = hp[bt + i];
#pragma unroll
            for (int j = 0; j < 4; j++) wv[j] = wp[nt + j];
#pragma unroll
            for (int i = 0; i < 4; i++)
#pragma unroll
                for (int j = 0; j < 4; j++)
                    acc[i][j] = fmaf(hv[i], wv[j], acc[i][j]);
            hp += 33; wp += 33;
        }
#pragma unroll
        for (int i = 0; i < 4; i++)
#pragma unroll
            for (int j = 0; j < 4; j++)
                red[(ks << 10) + ((bt + i) << 5) + nt + j] = acc[i][j];
        __syncthreads();

        // reduce k-splits + add pre-activation
#pragma unroll
        for (int ii = 0; ii < 4; ii++) {
            int o = tid + (ii << 8);
            gates[o] = red[o] + red[1024 + o] + red[2048 + o] + red[3072 + o] + gp[ii];
        }
        __syncthreads();

        // LSTM cell update for this thread's (b, j)
        {
            const float* gb = gates + (ab << 5);
            float i_s = sigm_(gb[ajl]);
            float f_s = sigm_(gb[8 + ajl]);
            float g_t = tanh_(gb[16 + ajl]);
            float o_s = sigm_(gb[24 + ajl]);
            c_reg = f_s * c_reg + i_s * g_t;
            float h = o_s * tanh_(c_reg);
            g_hbuf[d][(s + 1) & 1][(ab << 9) + j0 + ajl] = h;
            out[((size_t)(ab * S_ + t) << 10) + (d << 9) + j0 + ajl] = h;
            if (s == S_ - 1) {
                size_t fo = (size_t)(d * B_ + ab) * H_ + j0 + ajl;
                out[SH_OFF + fo] = h;
                out[SC_OFF + fo] = c_reg;
            }
        }
        __syncthreads();  // all h stores done (block-visible) before t0 releases

        // one grid barrier per step (per direction, 64 co-resident CTAs)
        if (tid == 0) {
            __threadfence();                      // cumulative release of block's writes
            atomicAdd(&g_bar[d], 1u);
            unsigned int target = 64u * (unsigned)(s + 1);
            volatile unsigned int* p = &g_bar[d];
            while (*p < target) __nanosleep(64);
            __threadfence();                      // acquire before releasing block
        }
        __syncthreads();
    }
}

// ---------------- launch ----------------
extern "C" void kernel_launch(void* const* d_in, const int* in_sizes, int n_in,
                              void* d_out, int out_size) {
    const float* X     = (const float*)d_in[0];
    const float* Wih_f = (const float*)d_in[1];
    const float* Whh_f = (const float*)d_in[2];
    const float* bih_f = (const float*)d_in[3];
    const float* bhh_f = (const float*)d_in[4];
    const float* Wih_b = (const float*)d_in[5];
    const float* Whh_b = (const float*)d_in[6];
    const float* bih_b = (const float*)d_in[7];
    const float* bhh_b = (const float*)d_in[8];
    float* out = (float*)d_out;

    static const size_t shbytes = (size_t)(2 * 512 * 33 + 4096 + 1024) * sizeof(float);
    cudaFuncSetAttribute(recur_kernel, cudaFuncAttributeMaxDynamicSharedMemorySize,
                         (int)shbytes);

    init_kernel<<<(2 * 2 * B_ * H_ + 255) / 256, 256>>>();
    xgemm_kernel<<<dim3(G4_ / 64, (B_ * S_) / 128, 2), 256>>>(
        X, Wih_f, bih_f, bhh_f, Wih_b, bih_b, bhh_b);
    recur_kernel<<<dim3(64, 2), 256, shbytes>>>(Whh_f, Whh_b, out);
}

// round 4
// speedup vs baseline: 1.1619x; 1.1619x over previous
#include <cuda_runtime.h>
#include <cuda_bf16.h>
#include <cstdint>

#define B_   32
#define S_   512
#define I_   512
#define H_   512
#define G4_  2048   // 4*H

#define SH_OFF   16777216u            // stacked_h offset in out
#define SC_OFF   (16777216u + 32768u) // stacked_c offset in out

// ---------------- device scratch (allocations are forbidden) ----------------
__device__ __align__(16) float g_pre[(size_t)2 * S_ * B_ * G4_]; // [dir][t][b][4H]
__device__ __align__(16) float g_hbuf[2][2][B_ * H_];            // [dir][buf][b*512+k]
__device__ unsigned int       g_bar[2];

// bf16 hi/lo splits of X and Wih (written by prep_kernel)
__device__ __align__(16) __nv_bfloat16 g_Xhi[8388608];
__device__ __align__(16) __nv_bfloat16 g_Xlo[8388608];
__device__ __align__(16) __nv_bfloat16 g_Whi[2097152];  // [dir][2048][512]
__device__ __align__(16) __nv_bfloat16 g_Wlo[2097152];

// ---------------- init: reset barrier + h state every launch ----------------
__global__ void init_kernel() {
    int idx = blockIdx.x * blockDim.x + threadIdx.x;
    if (idx < 2 * 2 * B_ * H_) ((float*)g_hbuf)[idx] = 0.0f;
    if (idx < 2) g_bar[idx] = 0u;
}

// ---------------- prep: split fp32 -> bf16 hi + lo ----------------
__device__ __forceinline__ void split2(float x, __nv_bfloat16& h, __nv_bfloat16& l) {
    h = __float2bfloat16(x);
    l = __float2bfloat16(x - __bfloat162float(h));
}

__global__ __launch_bounds__(256) void prep_kernel(
    const float* __restrict__ X, const float* __restrict__ Wf, const float* __restrict__ Wb)
{
    const int NXv = 8388608 / 4;
    const int NWv = 1048576 / 4;
    int i = blockIdx.x * 256 + threadIdx.x;

    const float* src;
    __nv_bfloat16 *dh, *dl;
    int o;
    if (i < NXv)                 { src = X;  dh = g_Xhi;            dl = g_Xlo;            o = i; }
    else if (i < NXv + NWv)      { src = Wf; dh = g_Whi;            dl = g_Wlo;            o = i - NXv; }
    else if (i < NXv + 2 * NWv)  { src = Wb; dh = g_Whi + 1048576;  dl = g_Wlo + 1048576;  o = i - NXv - NWv; }
    else return;

    float4 v = ((const float4*)src)[o];
    __nv_bfloat16 h0, l0, h1, l1, h2, l2, h3, l3;
    split2(v.x, h0, l0); split2(v.y, h1, l1);
    split2(v.z, h2, l2); split2(v.w, h3, l3);
    ((__nv_bfloat162*)dh)[2 * o]     = __nv_bfloat162{h0, h1};
    ((__nv_bfloat162*)dh)[2 * o + 1] = __nv_bfloat162{h2, h3};
    ((__nv_bfloat162*)dl)[2 * o]     = __nv_bfloat162{l0, l1};
    ((__nv_bfloat162*)dl)[2 * o + 1] = __nv_bfloat162{l2, l3};
}

// ---------------- tensor-core helpers ----------------
__device__ __forceinline__ void mma16816(float* c, const uint32_t* a, const uint32_t* b) {
    asm volatile(
        "mma.sync.aligned.m16n8k16.row.col.f32.bf16.bf16.f32 "
        "{%0,%1,%2,%3}, {%4,%5,%6,%7}, {%8,%9}, {%0,%1,%2,%3};"
        : "+f"(c[0]), "+f"(c[1]), "+f"(c[2]), "+f"(c[3])
        : "r"(a[0]), "r"(a[1]), "r"(a[2]), "r"(a[3]), "r"(b[0]), "r"(b[1]));
}
__device__ __forceinline__ void ldsm_x4(uint32_t* r, uint32_t addr) {
    asm volatile("ldmatrix.sync.aligned.m8n8.x4.shared.b16 {%0,%1,%2,%3}, [%4];"
                 : "=r"(r[0]), "=r"(r[1]), "=r"(r[2]), "=r"(r[3]) : "r"(addr));
}
__device__ __forceinline__ void ldsm_x2(uint32_t* r, uint32_t addr) {
    asm volatile("ldmatrix.sync.aligned.m8n8.x2.shared.b16 {%0,%1}, [%2];"
                 : "=r"(r[0]), "=r"(r[1]) : "r"(addr));
}
__device__ __forceinline__ void cpasync16(uint32_t dst, const void* src) {
    asm volatile("cp.async.cg.shared.global [%0], [%1], 16;" :: "r"(dst), "l"(src));
}
#define CP_COMMIT() asm volatile("cp.async.commit_group;")

// ---------------- phase 1: G = X @ Wih^T + (bih+bhh), bf16x2 split tensor GEMM ----
// CTA tile 128(m) x 128(n), K-tile 64, double-buffered cp.async.
// m = t*32 + b ; A row m is X[b][t][:]; output [d][t][b][4H].
// smem per buffer: As_hi[128][72], As_lo, Bs_hi, Bs_lo (bf16, pad 72) = 73728 B
__global__ __launch_bounds__(256) void xgemm_mma(
    const float* __restrict__ bih_f, const float* __restrict__ bhh_f,
    const float* __restrict__ bih_b, const float* __restrict__ bhh_b)
{
    extern __shared__ __nv_bfloat16 smem_bf[];
    const uint32_t smb = (uint32_t)__cvta_generic_to_shared(smem_bf);

    const int tid  = threadIdx.x;
    const int lane = tid & 31;
    const int warp = tid >> 5;
    const int d     = blockIdx.z;
    const int m_blk = blockIdx.y * 128;
    const int n_blk = blockIdx.x * 128;
    const int wm = (warp >> 2) * 64;   // 2 warps in m -> 64 rows each
    const int wn = (warp & 3) * 32;    // 4 warps in n -> 32 cols each

    const size_t wofs = (size_t)d * 1048576;

    float acc[4][4][4];
#pragma unroll
    for (int i = 0; i < 4; i++)
#pragma unroll
        for (int j = 0; j < 4; j++)
#pragma unroll
            for (int c = 0; c < 4; c++) acc[i][j][c] = 0.0f;

    const int lrow   = tid >> 3;        // 0..31
    const int lchunk = (tid & 7) << 3;  // elem 0..56

    // tile loader: A and B hi/lo (relative layout identical across the 4 arrays)
    auto load_tile = [&](int kt, int buf) {
        uint32_t base = smb + (uint32_t)buf * 73728u;
#pragma unroll
        for (int r = 0; r < 4; r++) {
            int row = lrow + r * 32;
            uint32_t dst = base + (uint32_t)(row * 72 + lchunk) * 2u;
            int m = m_blk + row;
            int bb = m & 31, tt = m >> 5;
            size_t aoff = (((size_t)bb * 512 + tt) << 9) + kt + lchunk;
            cpasync16(dst,          g_Xhi + aoff);
            cpasync16(dst + 18432u, g_Xlo + aoff);
            size_t boff = wofs + ((size_t)(n_blk + row) << 9) + kt + lchunk;
            cpasync16(dst + 36864u, g_Whi + boff);
            cpasync16(dst + 55296u, g_Wlo + boff);
        }
    };

    load_tile(0, 0);
    CP_COMMIT();

    int buf = 0;
    for (int it = 0; it < 8; it++) {
        if (it < 7) { load_tile((it + 1) * 64, buf ^ 1); CP_COMMIT(); }
        if (it < 7) asm volatile("cp.async.wait_group 1;");
        else        asm volatile("cp.async.wait_group 0;");
        __syncthreads();

        uint32_t bufb = smb + (uint32_t)buf * 73728u;
        const int l = lane & 15;
#pragma unroll
        for (int kf = 0; kf < 64; kf += 16) {
            uint32_t bh[4][2], bl[4][2];
            uint32_t brel = (uint32_t)(((wn + (l & 7)) * 72 + kf + ((l >> 3) << 3)) * 2);
#pragma unroll
            for (int fn = 0; fn < 4; fn++) {
                uint32_t ad = bufb + 36864u + brel + (uint32_t)(fn * 8 * 72 * 2);
                ldsm_x2(bh[fn], ad);
                ldsm_x2(bl[fn], ad + 18432u);
            }
            uint32_t arel = (uint32_t)(((wm + l) * 72 + kf + ((lane >> 4) << 3)) * 2);
#pragma unroll
            for (int fm = 0; fm < 4; fm++) {
                uint32_t aa = bufb + arel + (uint32_t)(fm * 16 * 72 * 2);
                uint32_t ah[4], al[4];
                ldsm_x4(ah, aa);
                ldsm_x4(al, aa + 18432u);
#pragma unroll
                for (int fn = 0; fn < 4; fn++) {
                    mma16816(acc[fm][fn], ah, bh[fn]);
                    mma16816(acc[fm][fn], ah, bl[fn]);
                    mma16816(acc[fm][fn], al, bh[fn]);
                }
            }
        }
        __syncthreads();
        buf ^= 1;
    }

    // epilogue: + (bih+bhh), store to g_pre[d][t][b][4H]
    const float* bi  = d ? bih_b : bih_f;
    const float* bhp = d ? bhh_b : bhh_f;
#pragma unroll
    for (int fn = 0; fn < 4; fn++) {
        int n = n_blk + wn + fn * 8 + ((lane & 3) << 1);
        float b0 = bi[n] + bhp[n];
        float b1 = bi[n + 1] + bhp[n + 1];
#pragma unroll
        for (int fm = 0; fm < 4; fm++) {
            int m = m_blk + wm + fm * 16 + (lane >> 2);
            int t0 = m >> 5, bb0 = m & 31;
            float2 v0 = make_float2(acc[fm][fn][0] + b0, acc[fm][fn][1] + b1);
            *(float2*)(g_pre + ((((size_t)d * 512 + t0) * 32 + bb0) << 11) + n) = v0;
            int m2 = m + 8;
            int t1 = m2 >> 5, bb1 = m2 & 31;
            float2 v1 = make_float2(acc[fm][fn][2] + b0, acc[fm][fn][3] + b1);
            *(float2*)(g_pre + ((((size_t)d * 512 + t1) * 32 + bb1) << 11) + n) = v1;
        }
    }
}

// ---------------- activations (fp32, ~2^-21 rel err) ----------------
__device__ __forceinline__ float sigm_(float x) {
    x = fminf(fmaxf(x, -30.0f), 30.0f);
    return __fdividef(1.0f, 1.0f + __expf(-x));
}
__device__ __forceinline__ float tanh_(float x) {
    x = fminf(fmaxf(x, -15.0f), 15.0f);
    float e = __expf(-2.0f * x);
    return __fdividef(1.0f - e, 1.0f + e);
}

// ---------------- phase 2: persistent recurrence (unchanged from R3) ----------------
__global__ __launch_bounds__(256, 1) void recur_kernel(
    const float* __restrict__ Whh_f, const float* __restrict__ Whh_b,
    float* __restrict__ out)
{
    extern __shared__ float sm[];
    float* whT   = sm;                 // [512][33]
    float* hsT   = sm + 512 * 33;      // [512][33]
    float* red   = sm + 2 * 512 * 33;  // [4][1024]
    float* gates = red + 4096;         // [1024]

    const int tid = threadIdx.x;
    const int q   = blockIdx.x;
    const int d   = blockIdx.y;
    const int j0  = q << 3;
    const float* __restrict__ Whh = d ? Whh_b : Whh_f;

    for (int e = tid; e < 32 * 512; e += 256) {
        int r = e >> 9, k = e & 511;
        int grow = ((r >> 3) << 9) + j0 + (r & 7);
        whT[k * 33 + r] = Whh[(size_t)grow * 512 + k];
    }

    const int tileIdx = tid & 63;
    const int ks = tid >> 6;
    const int bt = (tileIdx & 7) << 2;
    const int nt = (tileIdx >> 3) << 2;

    const int ab  = tid >> 3;
    const int ajl = tid & 7;
    float c_reg = 0.0f;

    for (int s = 0; s < S_; s++) {
        const int t = d ? (S_ - 1 - s) : s;

        const float* hsrc = &g_hbuf[d][s & 1][0];
        for (int e = tid; e < B_ * H_; e += 256) {
            int b = e >> 9, k = e & 511;
            hsT[k * 33 + b] = __ldcg(hsrc + e);
        }

        float gp[4];
        const float* gpt = g_pre + ((size_t)(d * S_ + t) * B_) * (size_t)G4_;
#pragma unroll
        for (int ii = 0; ii < 4; ii++) {
            int o = tid + (ii << 8);
            int b = o >> 5, r = o & 31;
            gp[ii] = gpt[(size_t)b * G4_ + ((r >> 3) << 9) + j0 + (r & 7)];
        }
        __syncthreads();

        float acc[4][4];
#pragma unroll
        for (int i = 0; i < 4; i++)
#pragma unroll
            for (int j = 0; j < 4; j++) acc[i][j] = 0.0f;

        const float* hp = hsT + ks * 128 * 33;
        const float* wp = whT + ks * 128 * 33;
#pragma unroll 4
        for (int k = 0; k < 128; k++) {
            float hv[4], wv[4];
#pragma unroll
            for (int i = 0; i < 4; i++) hv[i] = hp[bt + i];
#pragma unroll
            for (int j = 0; j < 4; j++) wv[j] = wp[nt + j];
#pragma unroll
            for (int i = 0; i < 4; i++)
#pragma unroll
                for (int j = 0; j < 4; j++)
                    acc[i][j] = fmaf(hv[i], wv[j], acc[i][j]);
            hp += 33; wp += 33;
        }
#pragma unroll
        for (int i = 0; i < 4; i++)
#pragma unroll
            for (int j = 0; j < 4; j++)
                red[(ks << 10) + ((bt + i) << 5) + nt + j] = acc[i][j];
        __syncthreads();

#pragma unroll
        for (int ii = 0; ii < 4; ii++) {
            int o = tid + (ii << 8);
            gates[o] = red[o] + red[1024 + o] + red[2048 + o] + red[3072 + o] + gp[ii];
        }
        __syncthreads();

        {
            const float* gb = gates + (ab << 5);
            float i_s = sigm_(gb[ajl]);
            float f_s = sigm_(gb[8 + ajl]);
            float g_t = tanh_(gb[16 + ajl]);
            float o_s = sigm_(gb[24 + ajl]);
            c_reg = f_s * c_reg + i_s * g_t;
            float h = o_s * tanh_(c_reg);
            g_hbuf[d][(s + 1) & 1][(ab << 9) + j0 + ajl] = h;
            out[((size_t)(ab * S_ + t) << 10) + (d << 9) + j0 + ajl] = h;
            if (s == S_ - 1) {
                size_t fo = (size_t)(d * B_ + ab) * H_ + j0 + ajl;
                out[SH_OFF + fo] = h;
                out[SC_OFF + fo] = c_reg;
            }
        }
        __syncthreads();

        if (tid == 0) {
            __threadfence();
            atomicAdd(&g_bar[d], 1u);
            unsigned int target = 64u * (unsigned)(s + 1);
            volatile unsigned int* p = &g_bar[d];
            while (*p < target) __nanosleep(64);
            __threadfence();
        }
        __syncthreads();
    }
}

// ---------------- launch ----------------
extern "C" void kernel_launch(void* const* d_in, const int* in_sizes, int n_in,
                              void* d_out, int out_size) {
    const float* X     = (const float*)d_in[0];
    const float* Wih_f = (const float*)d_in[1];
    const float* Whh_f = (const float*)d_in[2];
    const float* bih_f = (const float*)d_in[3];
    const float* bhh_f = (const float*)d_in[4];
    const float* Wih_b = (const float*)d_in[5];
    const float* Whh_b = (const float*)d_in[6];
    const float* bih_b = (const float*)d_in[7];
    const float* bhh_b = (const float*)d_in[8];
    float* out = (float*)d_out;

    static const size_t rec_sh = (size_t)(2 * 512 * 33 + 4096 + 1024) * sizeof(float);
    static const size_t gem_sh = 2 * 73728;
    cudaFuncSetAttribute(recur_kernel, cudaFuncAttributeMaxDynamicSharedMemorySize, (int)rec_sh);
    cudaFuncSetAttribute(xgemm_mma,    cudaFuncAttributeMaxDynamicSharedMemorySize, (int)gem_sh);

    init_kernel<<<(2 * 2 * B_ * H_ + 255) / 256, 256>>>();
    prep_kernel<<<(2097152 + 2 * 262144 + 255) / 256, 256>>>(X, Wih_f, Wih_b);
    xgemm_mma<<<dim3(G4_ / 128, (B_ * S_) / 128, 2), 256, gem_sh>>>(bih_f, bhh_f, bih_b, bhh_b);
    recur_kernel<<<dim3(64, 2), 256, rec_sh>>>(Whh_f, Whh_b, out);
}

// round 5
// speedup vs baseline: 2.2318x; 1.9207x over previous
#include <cuda_runtime.h>
#include <cuda_bf16.h>
#include <cstdint>

#define B_   32
#define S_   512
#define I_   512
#define H_   512
#define G4_  2048   // 4*H

#define SH_OFF   16777216u            // stacked_h offset in out
#define SC_OFF   (16777216u + 32768u) // stacked_c offset in out

#define RSTR 520                      // bf16 smem row stride (conflict-free for ldmatrix)

// ---------------- device scratch (allocations are forbidden) ----------------
__device__ __align__(16) float    g_pre[(size_t)2 * S_ * B_ * G4_]; // [dir][t][b][4H]
__device__ __align__(16) uint32_t g_hpk[2][2][B_ * H_];             // packed bf16 (hi|lo<<16)
__device__ unsigned int           g_bar[2];

// bf16 hi/lo splits (written by prep_kernel)
__device__ __align__(16) __nv_bfloat16 g_Xhi[8388608];
__device__ __align__(16) __nv_bfloat16 g_Xlo[8388608];
__device__ __align__(16) __nv_bfloat16 g_Whi[2097152];  // Wih  [dir][2048][512]
__device__ __align__(16) __nv_bfloat16 g_Wlo[2097152];
__device__ __align__(16) __nv_bfloat16 g_Uhi[2097152];  // Whh  [dir][2048][512]
__device__ __align__(16) __nv_bfloat16 g_Ulo[2097152];

// ---------------- init: reset barrier + h state every launch ----------------
__global__ void init_kernel() {
    int idx = blockIdx.x * blockDim.x + threadIdx.x;
    if (idx < 2 * 2 * B_ * H_) ((uint32_t*)g_hpk)[idx] = 0u;
    if (idx < 2) g_bar[idx] = 0u;
}

// ---------------- prep: split fp32 -> bf16 hi + lo ----------------
__device__ __forceinline__ void split2(float x, __nv_bfloat16& h, __nv_bfloat16& l) {
    h = __float2bfloat16(x);
    l = __float2bfloat16(x - __bfloat162float(h));
}

__global__ __launch_bounds__(256) void prep_kernel(
    const float* __restrict__ X,
    const float* __restrict__ Wf, const float* __restrict__ Wb,
    const float* __restrict__ Uf, const float* __restrict__ Ub)
{
    const int NXv = 8388608 / 4;
    const int NWv = 1048576 / 4;
    int i = blockIdx.x * 256 + threadIdx.x;

    const float* src;
    __nv_bfloat16 *dh, *dl;
    int o;
    if (i < NXv)                     { src = X;  dh = g_Xhi;           dl = g_Xlo;           o = i; }
    else if (i < NXv + NWv)          { src = Wf; dh = g_Whi;           dl = g_Wlo;           o = i - NXv; }
    else if (i < NXv + 2 * NWv)      { src = Wb; dh = g_Whi + 1048576; dl = g_Wlo + 1048576; o = i - NXv - NWv; }
    else if (i < NXv + 3 * NWv)      { src = Uf; dh = g_Uhi;           dl = g_Ulo;           o = i - NXv - 2 * NWv; }
    else if (i < NXv + 4 * NWv)      { src = Ub; dh = g_Uhi + 1048576; dl = g_Ulo + 1048576; o = i - NXv - 3 * NWv; }
    else return;

    float4 v = ((const float4*)src)[o];
    __nv_bfloat16 h0, l0, h1, l1, h2, l2, h3, l3;
    split2(v.x, h0, l0); split2(v.y, h1, l1);
    split2(v.z, h2, l2); split2(v.w, h3, l3);
    ((__nv_bfloat162*)dh)[2 * o]     = __nv_bfloat162{h0, h1};
    ((__nv_bfloat162*)dh)[2 * o + 1] = __nv_bfloat162{h2, h3};
    ((__nv_bfloat162*)dl)[2 * o]     = __nv_bfloat162{l0, l1};
    ((__nv_bfloat162*)dl)[2 * o + 1] = __nv_bfloat162{l2, l3};
}

// ---------------- tensor-core helpers ----------------
__device__ __forceinline__ void mma16816(float* c, const uint32_t* a, const uint32_t* b) {
    asm volatile(
        "mma.sync.aligned.m16n8k16.row.col.f32.bf16.bf16.f32 "
        "{%0,%1,%2,%3}, {%4,%5,%6,%7}, {%8,%9}, {%0,%1,%2,%3};"
        : "+f"(c[0]), "+f"(c[1]), "+f"(c[2]), "+f"(c[3])
        : "r"(a[0]), "r"(a[1]), "r"(a[2]), "r"(a[3]), "r"(b[0]), "r"(b[1]));
}
__device__ __forceinline__ void ldsm_x4(uint32_t* r, uint32_t addr) {
    asm volatile("ldmatrix.sync.aligned.m8n8.x4.shared.b16 {%0,%1,%2,%3}, [%4];"
                 : "=r"(r[0]), "=r"(r[1]), "=r"(r[2]), "=r"(r[3]) : "r"(addr));
}
__device__ __forceinline__ void ldsm_x2(uint32_t* r, uint32_t addr) {
    asm volatile("ldmatrix.sync.aligned.m8n8.x2.shared.b16 {%0,%1}, [%2];"
                 : "=r"(r[0]), "=r"(r[1]) : "r"(addr));
}
__device__ __forceinline__ void cpasync16(uint32_t dst, const void* src) {
    asm volatile("cp.async.cg.shared.global [%0], [%1], 16;" :: "r"(dst), "l"(src));
}
#define CP_COMMIT() asm volatile("cp.async.commit_group;")

// ---------------- phase 1: G = X @ Wih^T + (bih+bhh), split-bf16 MMA (as R4) ----
__global__ __launch_bounds__(256) void xgemm_mma(
    const float* __restrict__ bih_f, const float* __restrict__ bhh_f,
    const float* __restrict__ bih_b, const float* __restrict__ bhh_b)
{
    extern __shared__ __nv_bfloat16 smem_bf[];
    const uint32_t smb = (uint32_t)__cvta_generic_to_shared(smem_bf);

    const int tid  = threadIdx.x;
    const int lane = tid & 31;
    const int warp = tid >> 5;
    const int d     = blockIdx.z;
    const int m_blk = blockIdx.y * 128;
    const int n_blk = blockIdx.x * 128;
    const int wm = (warp >> 2) * 64;
    const int wn = (warp & 3) * 32;

    const size_t wofs = (size_t)d * 1048576;

    float acc[4][4][4];
#pragma unroll
    for (int i = 0; i < 4; i++)
#pragma unroll
        for (int j = 0; j < 4; j++)
#pragma unroll
            for (int c = 0; c < 4; c++) acc[i][j][c] = 0.0f;

    const int lrow   = tid >> 3;
    const int lchunk = (tid & 7) << 3;

    auto load_tile = [&](int kt, int buf) {
        uint32_t base = smb + (uint32_t)buf * 73728u;
#pragma unroll
        for (int r = 0; r < 4; r++) {
            int row = lrow + r * 32;
            uint32_t dst = base + (uint32_t)(row * 72 + lchunk) * 2u;
            int m = m_blk + row;
            int bb = m & 31, tt = m >> 5;
            size_t aoff = (((size_t)bb * 512 + tt) << 9) + kt + lchunk;
            cpasync16(dst,          g_Xhi + aoff);
            cpasync16(dst + 18432u, g_Xlo + aoff);
            size_t boff = wofs + ((size_t)(n_blk + row) << 9) + kt + lchunk;
            cpasync16(dst + 36864u, g_Whi + boff);
            cpasync16(dst + 55296u, g_Wlo + boff);
        }
    };

    load_tile(0, 0);
    CP_COMMIT();

    int buf = 0;
    for (int it = 0; it < 8; it++) {
        if (it < 7) { load_tile((it + 1) * 64, buf ^ 1); CP_COMMIT(); }
        if (it < 7) asm volatile("cp.async.wait_group 1;");
        else        asm volatile("cp.async.wait_group 0;");
        __syncthreads();

        uint32_t bufb = smb + (uint32_t)buf * 73728u;
        const int l = lane & 15;
#pragma unroll
        for (int kf = 0; kf < 64; kf += 16) {
            uint32_t bh[4][2], bl[4][2];
            uint32_t brel = (uint32_t)(((wn + (l & 7)) * 72 + kf + ((l >> 3) << 3)) * 2);
#pragma unroll
            for (int fn = 0; fn < 4; fn++) {
                uint32_t ad = bufb + 36864u + brel + (uint32_t)(fn * 8 * 72 * 2);
                ldsm_x2(bh[fn], ad);
                ldsm_x2(bl[fn], ad + 18432u);
            }
            uint32_t arel = (uint32_t)(((wm + l) * 72 + kf + ((lane >> 4) << 3)) * 2);
#pragma unroll
            for (int fm = 0; fm < 4; fm++) {
                uint32_t aa = bufb + arel + (uint32_t)(fm * 16 * 72 * 2);
                uint32_t ah[4], al[4];
                ldsm_x4(ah, aa);
                ldsm_x4(al, aa + 18432u);
#pragma unroll
                for (int fn = 0; fn < 4; fn++) {
                    mma16816(acc[fm][fn], ah, bh[fn]);
                    mma16816(acc[fm][fn], ah, bl[fn]);
                    mma16816(acc[fm][fn], al, bh[fn]);
                }
            }
        }
        __syncthreads();
        buf ^= 1;
    }

    const float* bi  = d ? bih_b : bih_f;
    const float* bhp = d ? bhh_b : bhh_f;
#pragma unroll
    for (int fn = 0; fn < 4; fn++) {
        int n = n_blk + wn + fn * 8 + ((lane & 3) << 1);
        float b0 = bi[n] + bhp[n];
        float b1 = bi[n + 1] + bhp[n + 1];
#pragma unroll
        for (int fm = 0; fm < 4; fm++) {
            int m = m_blk + wm + fm * 16 + (lane >> 2);
            int t0 = m >> 5, bb0 = m & 31;
            float2 v0 = make_float2(acc[fm][fn][0] + b0, acc[fm][fn][1] + b1);
            *(float2*)(g_pre + ((((size_t)d * 512 + t0) * 32 + bb0) << 11) + n) = v0;
            int m2 = m + 8;
            int t1 = m2 >> 5, bb1 = m2 & 31;
            float2 v1 = make_float2(acc[fm][fn][2] + b0, acc[fm][fn][3] + b1);
            *(float2*)(g_pre + ((((size_t)d * 512 + t1) * 32 + bb1) << 11) + n) = v1;
        }
    }
}

// ---------------- activations (fp32, ~2^-21 rel err) ----------------
__device__ __forceinline__ float sigm_(float x) {
    x = fminf(fmaxf(x, -30.0f), 30.0f);
    return __fdividef(1.0f, 1.0f + __expf(-x));
}
__device__ __forceinline__ float tanh_(float x) {
    x = fminf(fmaxf(x, -15.0f), 15.0f);
    float e = __expf(-2.0f * x);
    return __fdividef(1.0f - e, 1.0f + e);
}

// ---------------- phase 2: persistent recurrence, tensor-core h@Whh^T ----------------
// grid (64, 2). CTA (q,d) owns 8 hidden units (32 gate rows). Per step:
// C[32b x 32r] = h[32x512] @ Whh_slice^T via split-bf16 mma (3 passes).
// smem: Whi[32][520], Wlo, hHi[32][520], hLo (bf16) + gates[32][33] (f32) = 137344 B
__global__ __launch_bounds__(256, 1) void recur_kernel(float* __restrict__ out)
{
    extern __shared__ __nv_bfloat16 smr[];
    __nv_bfloat16* WhiS = smr;
    __nv_bfloat16* WloS = smr + 32 * RSTR;
    __nv_bfloat16* hHiS = smr + 2 * 32 * RSTR;
    __nv_bfloat16* hLoS = smr + 3 * 32 * RSTR;
    float* gatesS = (float*)(smr + 4 * 32 * RSTR);  // [32][33]

    const int tid  = threadIdx.x;
    const int lane = tid & 31;
    const int warp = tid >> 5;
    const int q = blockIdx.x;          // 0..63
    const int d = blockIdx.y;          // 0..1
    const int j0 = q << 3;

    // one-time: load this CTA's Whh slice (hi/lo) into smem
    const __nv_bfloat16* Uh = g_Uhi + (size_t)d * 1048576;
    const __nv_bfloat16* Ul = g_Ulo + (size_t)d * 1048576;
    for (int e = tid; e < 4096; e += 256) {
        int r = e >> 7;
        int k = (e & 127) << 2;
        int grow = ((r >> 3) << 9) + j0 + (r & 7);
        size_t so = (size_t)grow * 512 + k;
        *(uint2*)&WhiS[r * RSTR + k] = *(const uint2*)(Uh + so);
        *(uint2*)&WloS[r * RSTR + k] = *(const uint2*)(Ul + so);
    }

    const uint32_t smb  = (uint32_t)__cvta_generic_to_shared(smr);
    const uint32_t WhiA = smb;
    const uint32_t WloA = smb + 32 * RSTR * 2;
    const uint32_t hHiA = smb + 2 * 32 * RSTR * 2;
    const uint32_t hLoA = smb + 3 * 32 * RSTR * 2;

    // warp MMA footprint: C tile [16 x 8] at (m0, n0)
    const int m0 = (warp & 1) << 4;
    const int n0 = (warp >> 1) << 3;
    const int l  = lane & 15;
    const uint32_t aRel = (uint32_t)(((m0 + l) * RSTR + ((lane >> 4) << 3)) * 2);
    const uint32_t bRel = (uint32_t)(((n0 + (l & 7)) * RSTR + ((l >> 3) << 3)) * 2);

    // cell ownership: (b, j)
    const int ab = tid >> 3, ajl = tid & 7;
    float c_reg = 0.0f;

    for (int s = 0; s < S_; s++) {
        const int t = d ? (S_ - 1 - s) : s;

        // 1. load packed h (u32 = hi | lo<<16), split into smem bf16 planes
        const uint32_t* hsrc = g_hpk[d][s & 1];
#pragma unroll
        for (int it = 0; it < 16; it++) {
            int e4 = tid + (it << 8);        // 0..4095 (uint4 index)
            int b  = e4 >> 7;
            int k  = (e4 & 127) << 2;
            uint4 v = __ldcg((const uint4*)hsrc + e4);
            uint32_t hi01 = (v.x & 0xFFFFu) | (v.y << 16);
            uint32_t lo01 = (v.x >> 16)     | (v.y & 0xFFFF0000u);
            uint32_t hi23 = (v.z & 0xFFFFu) | (v.w << 16);
            uint32_t lo23 = (v.z >> 16)     | (v.w & 0xFFFF0000u);
            uint32_t off = (uint32_t)(b * RSTR + k);
            *(uint2*)&hHiS[off] = make_uint2(hi01, hi23);
            *(uint2*)&hLoS[off] = make_uint2(lo01, lo23);
        }

        // prefetch this step's pre-activations (4 gates of this thread's cell)
        const float* gpt = g_pre + (((size_t)(d * S_ + t) * B_ + ab) << 11) + j0 + ajl;
        float gp0 = __ldg(gpt);
        float gp1 = __ldg(gpt + 512);
        float gp2 = __ldg(gpt + 1024);
        float gp3 = __ldg(gpt + 1536);

        __syncthreads();

        // 2. split-bf16 tensor GEMM
        float c[4] = {0.f, 0.f, 0.f, 0.f};
#pragma unroll 8
        for (int ks = 0; ks < 32; ks++) {
            uint32_t koff = (uint32_t)(ks << 5);  // 16 bf16 * 2B
            uint32_t ah[4], al[4], bh[2], bl[2];
            ldsm_x4(ah, hHiA + aRel + koff);
            ldsm_x4(al, hLoA + aRel + koff);
            ldsm_x2(bh, WhiA + bRel + koff);
            ldsm_x2(bl, WloA + bRel + koff);
            mma16816(c, ah, bh);
            mma16816(c, ah, bl);
            mma16816(c, al, bh);
        }

        // 3. frags -> smem gates
        {
            int row = m0 + (lane >> 2);
            int col = n0 + ((lane & 3) << 1);
            gatesS[row * 33 + col]           = c[0];
            gatesS[row * 33 + col + 1]       = c[1];
            gatesS[(row + 8) * 33 + col]     = c[2];
            gatesS[(row + 8) * 33 + col + 1] = c[3];
        }
        __syncthreads();

        // 4. LSTM cell update
        {
            const float* gb = gatesS + ab * 33;
            float i_s = sigm_(gb[ajl]      + gp0);
            float f_s = sigm_(gb[8 + ajl]  + gp1);
            float g_t = tanh_(gb[16 + ajl] + gp2);
            float o_s = sigm_(gb[24 + ajl] + gp3);
            c_reg = f_s * c_reg + i_s * g_t;
            float h = o_s * tanh_(c_reg);

            __nv_bfloat16 hh = __float2bfloat16(h);
            __nv_bfloat16 hl = __float2bfloat16(h - __bfloat162float(hh));
            uint32_t pk = ((uint32_t)__bfloat16_as_ushort(hl) << 16) |
                          (uint32_t)__bfloat16_as_ushort(hh);
            g_hpk[d][(s + 1) & 1][(ab << 9) + j0 + ajl] = pk;

            out[((size_t)(ab * S_ + t) << 10) + (d << 9) + j0 + ajl] = h;
            if (s == S_ - 1) {
                size_t fo = (size_t)(d * B_ + ab) * H_ + j0 + ajl;
                out[SH_OFF + fo] = h;
                out[SC_OFF + fo] = c_reg;
            }
        }
        __syncthreads();

        // 5. one grid barrier per step (64 co-resident CTAs per direction)
        if (tid == 0) {
            __threadfence();
            atomicAdd(&g_bar[d], 1u);
            unsigned int target = 64u * (unsigned)(s + 1);
            volatile unsigned int* p = &g_bar[d];
            while (*p < target) __nanosleep(32);
            __threadfence();
        }
        __syncthreads();
    }
}

// ---------------- launch ----------------
extern "C" void kernel_launch(void* const* d_in, const int* in_sizes, int n_in,
                              void* d_out, int out_size) {
    const float* X     = (const float*)d_in[0];
    const float* Wih_f = (const float*)d_in[1];
    const float* Whh_f = (const float*)d_in[2];
    const float* bih_f = (const float*)d_in[3];
    const float* bhh_f = (const float*)d_in[4];
    const float* Wih_b = (const float*)d_in[5];
    const float* Whh_b = (const float*)d_in[6];
    const float* bih_b = (const float*)d_in[7];
    const float* bhh_b = (const float*)d_in[8];
    float* out = (float*)d_out;

    static const size_t rec_sh = (size_t)(4 * 32 * RSTR) * 2 + 32 * 33 * 4; // 137344
    static const size_t gem_sh = 2 * 73728;
    cudaFuncSetAttribute(recur_kernel, cudaFuncAttributeMaxDynamicSharedMemorySize, (int)rec_sh);
    cudaFuncSetAttribute(xgemm_mma,    cudaFuncAttributeMaxDynamicSharedMemorySize, (int)gem_sh);

    init_kernel<<<(2 * 2 * B_ * H_ + 255) / 256, 256>>>();
    prep_kernel<<<(2097152 + 4 * 262144 + 255) / 256, 256>>>(X, Wih_f, Wih_b, Whh_f, Whh_b);
    xgemm_mma<<<dim3(G4_ / 128, (B_ * S_) / 128, 2), 256, gem_sh>>>(bih_f, bhh_f, bih_b, bhh_b);
    recur_kernel<<<dim3(64, 2), 256, rec_sh>>>(out);
}